// round 15
// baseline (speedup 1.0000x reference)
#include <cuda_runtime.h>
#include <cstdint>

#define N 8192
#define THREADS 256
#define ROWS_PER_BLOCK 8
#define KCHUNK 2048
#define NCHUNK (N / KCHUNK)                 // 4
#define ROWGROUPS (N / ROWS_PER_BLOCK)      // 1024
#define GRID (ROWGROUPS * NCHUNK)           // 4096
#define ITERS8 (KCHUNK / (32 * 8))          // 8 float8 iters per lane
#define KEEP_ROWS 3584                      // 3584 * 32KB = 112 MB pinned in L2

__device__ float g_part[NCHUNK * N];

__device__ __forceinline__ float fast_tanh(float v)
{
    float o;
    asm("tanh.approx.f32 %0, %1;" : "=f"(o) : "f"(v));
    return o;
}

struct F8 { float4 lo, hi; };

// 256-bit load, keep-resident in L2 across graph replays.
__device__ __forceinline__ F8 ld_keep8(const float* p)
{
    unsigned long long a, b, c, d;
    asm volatile("ld.global.nc.L2::evict_last.v4.b64 {%0,%1,%2,%3}, [%4];"
                 : "=l"(a), "=l"(b), "=l"(c), "=l"(d) : "l"(p));
    F8 r;
    r.lo.x = __uint_as_float((unsigned)(a));       r.lo.y = __uint_as_float((unsigned)(a >> 32));
    r.lo.z = __uint_as_float((unsigned)(b));       r.lo.w = __uint_as_float((unsigned)(b >> 32));
    r.hi.x = __uint_as_float((unsigned)(c));       r.hi.y = __uint_as_float((unsigned)(c >> 32));
    r.hi.z = __uint_as_float((unsigned)(d));       r.hi.w = __uint_as_float((unsigned)(d >> 32));
    return r;
}

// 256-bit load, stream through L2 (don't displace the resident set).
__device__ __forceinline__ F8 ld_stream8(const float* p)
{
    unsigned long long a, b, c, d;
    asm volatile("ld.global.nc.L2::evict_first.v4.b64 {%0,%1,%2,%3}, [%4];"
                 : "=l"(a), "=l"(b), "=l"(c), "=l"(d) : "l"(p));
    F8 r;
    r.lo.x = __uint_as_float((unsigned)(a));       r.lo.y = __uint_as_float((unsigned)(a >> 32));
    r.lo.z = __uint_as_float((unsigned)(b));       r.lo.w = __uint_as_float((unsigned)(b >> 32));
    r.hi.x = __uint_as_float((unsigned)(c));       r.hi.y = __uint_as_float((unsigned)(c >> 32));
    r.hi.z = __uint_as_float((unsigned)(d));       r.hi.w = __uint_as_float((unsigned)(d >> 32));
    return r;
}

__device__ __forceinline__ float dot8(const F8& w, const float4& v0, const float4& v1)
{
    return (w.lo.x * v0.x + w.lo.y * v0.y + w.lo.z * v0.z + w.lo.w * v0.w)
         + (w.hi.x * v1.x + w.hi.y * v1.y + w.hi.z * v1.z + w.hi.w * v1.w);
}

template <bool KEEP>
__device__ __forceinline__ float dot_chunk(const float* __restrict__ Wrow,
                                           const float4* __restrict__ rs4,
                                           int lane)
{
    float a0 = 0.f, a1 = 0.f, a2 = 0.f, a3 = 0.f;
    #pragma unroll
    for (int i = 0; i < ITERS8; i += 4) {
        // 4 x 32B loads in flight per lane (4096 B in flight per warp).
        F8 w0 = KEEP ? ld_keep8(Wrow + ((i + 0) * 32 + lane) * 8)
                     : ld_stream8(Wrow + ((i + 0) * 32 + lane) * 8);
        F8 w1 = KEEP ? ld_keep8(Wrow + ((i + 1) * 32 + lane) * 8)
                     : ld_stream8(Wrow + ((i + 1) * 32 + lane) * 8);
        F8 w2 = KEEP ? ld_keep8(Wrow + ((i + 2) * 32 + lane) * 8)
                     : ld_stream8(Wrow + ((i + 2) * 32 + lane) * 8);
        F8 w3 = KEEP ? ld_keep8(Wrow + ((i + 3) * 32 + lane) * 8)
                     : ld_stream8(Wrow + ((i + 3) * 32 + lane) * 8);
        a0 += dot8(w0, rs4[((i + 0) * 32 + lane) * 2 + 0], rs4[((i + 0) * 32 + lane) * 2 + 1]);
        a1 += dot8(w1, rs4[((i + 1) * 32 + lane) * 2 + 0], rs4[((i + 1) * 32 + lane) * 2 + 1]);
        a2 += dot8(w2, rs4[((i + 2) * 32 + lane) * 2 + 0], rs4[((i + 2) * 32 + lane) * 2 + 1]);
        a3 += dot8(w3, rs4[((i + 3) * 32 + lane) * 2 + 0], rs4[((i + 3) * 32 + lane) * 2 + 1]);
    }
    return (a0 + a1) + (a2 + a3);
}

__global__ __launch_bounds__(THREADS) void gemv_partial_kernel(
    const float* __restrict__ y,
    const float* __restrict__ W)
{
    __shared__ float r_s[KCHUNK];  // 8 KB

    const int tid   = threadIdx.x;
    const int bx    = blockIdx.x;
    const int chunk = bx >> 10;          // bx / ROWGROUPS (chunk-major)
    const int rowg  = bx & (ROWGROUPS - 1);
    const int col0  = chunk * KCHUNK;

    // Stage r-chunk with single-instruction MUFU tanh.
    {
        const float4* ysrc = reinterpret_cast<const float4*>(y + col0);
        float4* rdst = reinterpret_cast<float4*>(r_s);
        #pragma unroll
        for (int i = tid; i < KCHUNK / 4; i += THREADS) {
            float4 v = ysrc[i];
            float4 t;
            t.x = fast_tanh(v.x); t.y = fast_tanh(v.y);
            t.z = fast_tanh(v.z); t.w = fast_tanh(v.w);
            rdst[i] = t;
        }
    }
    __syncthreads();

    const int warp = tid >> 5;
    const int lane = tid & 31;
    const int row  = rowg * ROWS_PER_BLOCK + warp;

    const float* __restrict__ Wrow = W + (size_t)row * N + col0;
    const float4* rs4 = reinterpret_cast<const float4*>(r_s);

    // Rows < KEEP_ROWS form the L2-resident set (hits on every graph replay).
    float acc = (row < KEEP_ROWS) ? dot_chunk<true >(Wrow, rs4, lane)
                                  : dot_chunk<false>(Wrow, rs4, lane);

    #pragma unroll
    for (int off = 16; off > 0; off >>= 1)
        acc += __shfl_xor_sync(0xFFFFFFFFu, acc, off);

    if (lane == 0)
        __stcg(&g_part[chunk * N + row], acc);
}

__global__ void epilogue_kernel(
    const float* __restrict__ x,
    const float* __restrict__ y,
    float* __restrict__ out)
{
    int i = blockIdx.x * blockDim.x + threadIdx.x;
    float xi = x[i];   // independent of GEMV
    float yi = y[i];

    cudaGridDependencySynchronize();

    float acc = g_part[0 * N + i] + g_part[1 * N + i]
              + g_part[2 * N + i] + g_part[3 * N + i];
    const float DT  = 1e-3f;
    const float TAU = 1e-2f;
    out[i] = yi + DT * ((-yi + acc + xi) / TAU);
}

extern "C" void kernel_launch(void* const* d_in, const int* in_sizes, int n_in,
                              void* d_out, int out_size)
{
    const float* x = (const float*)d_in[0];
    const float* y = (const float*)d_in[1];
    const float* W = (const float*)d_in[2];
    float* out = (float*)d_out;

    gemv_partial_kernel<<<GRID, THREADS>>>(y, W);

    cudaLaunchConfig_t cfg = {};
    cfg.gridDim  = dim3(N / THREADS);   // 32
    cfg.blockDim = dim3(THREADS);
    cfg.stream   = 0;
    cudaLaunchAttribute attr[1];
    attr[0].id = cudaLaunchAttributeProgrammaticStreamSerialization;
    attr[0].val.programmaticStreamSerializationAllowed = 1;
    cfg.attrs    = attr;
    cfg.numAttrs = 1;
    cudaLaunchKernelEx(&cfg, epilogue_kernel, x, y, out);
}

// round 16
// speedup vs baseline: 1.0091x; 1.0091x over previous
#include <cuda_runtime.h>

#define N 8192
#define THREADS 256
#define ROWS_PER_BLOCK 8
#define KCHUNK 1024
#define NCHUNK (N / KCHUNK)                 // 8
#define ROWGROUPS (N / ROWS_PER_BLOCK)      // 1024
#define GRID (ROWGROUPS * NCHUNK)           // 8192
#define ITERS (KCHUNK / (32 * 4))           // 8 float4 iters per lane

__device__ float g_part[NCHUNK * N];

__device__ __forceinline__ float fast_tanh(float v)
{
    float o;
    asm("tanh.approx.f32 %0, %1;" : "=f"(o) : "f"(v));
    return o;
}

__global__ __launch_bounds__(THREADS) void gemv_partial_kernel(
    const float* __restrict__ y,
    const float* __restrict__ W)
{
    __shared__ float r_s[KCHUNK];  // 4 KB

    const int tid   = threadIdx.x;
    const int bx    = blockIdx.x;
    const int chunk = bx >> 10;          // bx / ROWGROUPS (chunk-major)
    const int rowg  = bx & (ROWGROUPS - 1);
    const int col0  = chunk * KCHUNK;

    // Stage r-chunk (4 KB): one float4 per thread, tanh via MUFU.
    {
        const float4* ysrc = reinterpret_cast<const float4*>(y + col0);
        float4* rdst = reinterpret_cast<float4*>(r_s);
        float4 v = ysrc[tid];            // KCHUNK/4 == THREADS
        float4 t;
        t.x = fast_tanh(v.x); t.y = fast_tanh(v.y);
        t.z = fast_tanh(v.z); t.w = fast_tanh(v.w);
        rdst[tid] = t;
    }
    __syncthreads();

    const int warp = tid >> 5;
    const int lane = tid & 31;
    const int row  = rowg * ROWS_PER_BLOCK + warp;

    const float4* __restrict__ Wrow =
        reinterpret_cast<const float4*>(W + (size_t)row * N + col0);
    const float4* rs4 = reinterpret_cast<const float4*>(r_s);

    float a0 = 0.f, a1 = 0.f, a2 = 0.f, a3 = 0.f;
    #pragma unroll
    for (int i = 0; i < ITERS; i += 4) {
        float4 w0 = Wrow[(i + 0) * 32 + lane];
        float4 w1 = Wrow[(i + 1) * 32 + lane];
        float4 w2 = Wrow[(i + 2) * 32 + lane];
        float4 w3 = Wrow[(i + 3) * 32 + lane];
        float4 v0 = rs4[(i + 0) * 32 + lane];
        float4 v1 = rs4[(i + 1) * 32 + lane];
        float4 v2 = rs4[(i + 2) * 32 + lane];
        float4 v3 = rs4[(i + 3) * 32 + lane];
        a0 += w0.x * v0.x + w0.y * v0.y + w0.z * v0.z + w0.w * v0.w;
        a1 += w1.x * v1.x + w1.y * v1.y + w1.z * v1.z + w1.w * v1.w;
        a2 += w2.x * v2.x + w2.y * v2.y + w2.z * v2.z + w2.w * v2.w;
        a3 += w3.x * v3.x + w3.y * v3.y + w3.z * v3.z + w3.w * v3.w;
    }
    float acc = (a0 + a1) + (a2 + a3);

    #pragma unroll
    for (int off = 16; off > 0; off >>= 1)
        acc += __shfl_xor_sync(0xFFFFFFFFu, acc, off);

    if (lane == 0)
        __stcg(&g_part[chunk * N + row], acc);
}

__global__ void epilogue_kernel(
    const float* __restrict__ x,
    const float* __restrict__ y,
    float* __restrict__ out)
{
    int i = blockIdx.x * blockDim.x + threadIdx.x;
    float xi = x[i];   // independent of GEMV
    float yi = y[i];

    cudaGridDependencySynchronize();

    float acc = ((g_part[0 * N + i] + g_part[1 * N + i])
               + (g_part[2 * N + i] + g_part[3 * N + i]))
              + ((g_part[4 * N + i] + g_part[5 * N + i])
               + (g_part[6 * N + i] + g_part[7 * N + i]));
    const float DT  = 1e-3f;
    const float TAU = 1e-2f;
    out[i] = yi + DT * ((-yi + acc + xi) / TAU);
}

extern "C" void kernel_launch(void* const* d_in, const int* in_sizes, int n_in,
                              void* d_out, int out_size)
{
    const float* x = (const float*)d_in[0];
    const float* y = (const float*)d_in[1];
    const float* W = (const float*)d_in[2];
    float* out = (float*)d_out;

    gemv_partial_kernel<<<GRID, THREADS>>>(y, W);

    cudaLaunchConfig_t cfg = {};
    cfg.gridDim  = dim3(N / THREADS);   // 32
    cfg.blockDim = dim3(THREADS);
    cfg.stream   = 0;
    cudaLaunchAttribute attr[1];
    attr[0].id = cudaLaunchAttributeProgrammaticStreamSerialization;
    attr[0].val.programmaticStreamSerializationAllowed = 1;
    cfg.attrs    = attr;
    cfg.numAttrs = 1;
    cudaLaunchKernelEx(&cfg, epilogue_kernel, x, y, out);
}